// round 8
// baseline (speedup 1.0000x reference)
#include <cuda_runtime.h>

// FAC 3x3 dynamic filtering + LeakyReLU(0.2)
// feature: [N=8, C=64, H=128, W=128] f32
// filters: [N, C*9, H, W] f32, channel index = c*9 + t, tap t = kh*3 + kw (row-major)
// out[n,c,h,w] = sum_{kh,kw} feat_zeropad[n,c,h+kh-1,w+kw-1] * filt[n,c*9+kh*3+kw,h,w]
// then leaky relu slope 0.2.

#define N_ 8
#define C_ 64
#define H_ 128
#define W_ 128
#define HW_ (H_ * W_)

__global__ __launch_bounds__(256) void fac_leaky_kernel(
    const float* __restrict__ feat,
    const float* __restrict__ filt,
    float* __restrict__ out)
{
    // One thread = 4 consecutive output pixels (float4 along W).
    int idx = blockIdx.x * blockDim.x + threadIdx.x;  // over N*C*H*(W/4) = 2,097,152
    int w4 = idx & 31;            // W/4 = 32
    int h  = (idx >> 5) & 127;
    int nc = idx >> 12;           // n*C + c, 0..511
    int w  = w4 << 2;

    const float* fplane = feat + nc * HW_;
    // filters linear: (nc*9 + t)*HW + h*W + w  (16B aligned: w%4==0)
    const float* filbase = filt + (size_t)nc * 9 * HW_ + h * W_ + w;

    float4 acc = make_float4(0.f, 0.f, 0.f, 0.f);

    #pragma unroll
    for (int kh = 0; kh < 3; kh++) {
        int row = h + kh - 1;
        float e0, e1, e2, e3, e4, e5;   // feature cols w-1 .. w+4
        if (row >= 0 && row < H_) {
            const float* r = fplane + row * W_ + w;
            float4 mid = __ldg(reinterpret_cast<const float4*>(r));  // w..w+3, aligned
            e1 = mid.x; e2 = mid.y; e3 = mid.z; e4 = mid.w;
            e0 = (w > 0)        ? __ldg(r - 1) : 0.f;
            e5 = (w + 4 < W_)   ? __ldg(r + 4) : 0.f;
        } else {
            e0 = e1 = e2 = e3 = e4 = e5 = 0.f;
        }

        // kw = 0: pixel p uses e[p];   kw = 1: e[p+1];   kw = 2: e[p+2]
        {
            float4 f = __ldg(reinterpret_cast<const float4*>(filbase + (kh * 3 + 0) * HW_));
            acc.x = fmaf(e0, f.x, acc.x);
            acc.y = fmaf(e1, f.y, acc.y);
            acc.z = fmaf(e2, f.z, acc.z);
            acc.w = fmaf(e3, f.w, acc.w);
        }
        {
            float4 f = __ldg(reinterpret_cast<const float4*>(filbase + (kh * 3 + 1) * HW_));
            acc.x = fmaf(e1, f.x, acc.x);
            acc.y = fmaf(e2, f.y, acc.y);
            acc.z = fmaf(e3, f.z, acc.z);
            acc.w = fmaf(e4, f.w, acc.w);
        }
        {
            float4 f = __ldg(reinterpret_cast<const float4*>(filbase + (kh * 3 + 2) * HW_));
            acc.x = fmaf(e2, f.x, acc.x);
            acc.y = fmaf(e3, f.y, acc.y);
            acc.z = fmaf(e4, f.z, acc.z);
            acc.w = fmaf(e5, f.w, acc.w);
        }
    }

    // LeakyReLU(0.2)
    acc.x = (acc.x >= 0.f) ? acc.x : 0.2f * acc.x;
    acc.y = (acc.y >= 0.f) ? acc.y : 0.2f * acc.y;
    acc.z = (acc.z >= 0.f) ? acc.z : 0.2f * acc.z;
    acc.w = (acc.w >= 0.f) ? acc.w : 0.2f * acc.w;

    *reinterpret_cast<float4*>(out + nc * HW_ + h * W_ + w) = acc;
}

extern "C" void kernel_launch(void* const* d_in, const int* in_sizes, int n_in,
                              void* d_out, int out_size)
{
    const float* feat = (const float*)d_in[0];   // [8,64,128,128]
    const float* filt = (const float*)d_in[1];   // [8,576,128,128]
    float* out = (float*)d_out;                  // [8,64,128,128]

    // total float4 outputs = 8*64*128*32 = 2,097,152 -> 8192 blocks of 256
    fac_leaky_kernel<<<8192, 256>>>(feat, filt, out);
}

// round 9
// speedup vs baseline: 1.1732x; 1.1732x over previous
#include <cuda_runtime.h>

// FAC 3x3 dynamic filtering + LeakyReLU(0.2)
// feature: [N=8, C=64, H=128, W=128] f32
// filters: [N, C*9, H, W] f32, channel index = c*9 + t, tap t = kh*3 + kw (row-major)
// out[n,c,h,w] = sum_{kh,kw} feat_zeropad[n,c,h+kh-1,w+kw-1] * filt[n,c*9+kh*3+kw,h,w]
// then leaky relu slope 0.2.
//
// Mapping: one warp = one (n,c,h) row. 32 lanes x 4 pixels = 128 = W.
// Horizontal halo comes from warp shuffles instead of extra loads; all
// control flow is warp-uniform. Filters streamed with evict-first hint.

#define N_ 8
#define C_ 64
#define H_ 128
#define W_ 128
#define HW_ (H_ * W_)

__global__ __launch_bounds__(256) void fac_leaky_kernel(
    const float* __restrict__ feat,
    const float* __restrict__ filt,
    float* __restrict__ out)
{
    int idx  = blockIdx.x * blockDim.x + threadIdx.x;
    int lane = idx & 31;
    int wrp  = idx >> 5;          // 65536 warps total
    int h    = wrp & 127;
    int nc   = wrp >> 7;          // 0..511
    int w    = lane << 2;

    const float* fplane  = feat + nc * HW_;
    const float* filbase = filt + (size_t)nc * 9 * HW_ + h * W_ + w;

    float4 acc = make_float4(0.f, 0.f, 0.f, 0.f);

    #pragma unroll
    for (int kh = 0; kh < 3; kh++) {
        int row = h + kh - 1;                       // warp-uniform
        float e0, e1, e2, e3, e4, e5;               // feature cols w-1 .. w+4
        if (row >= 0 && row < H_) {
            float4 mid = __ldg(reinterpret_cast<const float4*>(fplane + row * W_ + w));
            e1 = mid.x; e2 = mid.y; e3 = mid.z; e4 = mid.w;
            // halo from neighbor lanes; zero at row ends (zero padding)
            e0 = __shfl_up_sync(0xFFFFFFFFu, mid.w, 1);
            e5 = __shfl_down_sync(0xFFFFFFFFu, mid.x, 1);
            if (lane == 0)  e0 = 0.f;
            if (lane == 31) e5 = 0.f;
        } else {
            e0 = e1 = e2 = e3 = e4 = e5 = 0.f;
        }

        // filters: streaming loads, evict-first (no reuse)
        {
            float4 f = __ldcs(reinterpret_cast<const float4*>(filbase + (kh * 3 + 0) * HW_));
            acc.x = fmaf(e0, f.x, acc.x);
            acc.y = fmaf(e1, f.y, acc.y);
            acc.z = fmaf(e2, f.z, acc.z);
            acc.w = fmaf(e3, f.w, acc.w);
        }
        {
            float4 f = __ldcs(reinterpret_cast<const float4*>(filbase + (kh * 3 + 1) * HW_));
            acc.x = fmaf(e1, f.x, acc.x);
            acc.y = fmaf(e2, f.y, acc.y);
            acc.z = fmaf(e3, f.z, acc.z);
            acc.w = fmaf(e4, f.w, acc.w);
        }
        {
            float4 f = __ldcs(reinterpret_cast<const float4*>(filbase + (kh * 3 + 2) * HW_));
            acc.x = fmaf(e2, f.x, acc.x);
            acc.y = fmaf(e3, f.y, acc.y);
            acc.z = fmaf(e4, f.z, acc.z);
            acc.w = fmaf(e5, f.w, acc.w);
        }
    }

    // LeakyReLU(0.2)
    acc.x = (acc.x >= 0.f) ? acc.x : 0.2f * acc.x;
    acc.y = (acc.y >= 0.f) ? acc.y : 0.2f * acc.y;
    acc.z = (acc.z >= 0.f) ? acc.z : 0.2f * acc.z;
    acc.w = (acc.w >= 0.f) ? acc.w : 0.2f * acc.w;

    __stcs(reinterpret_cast<float4*>(out + nc * HW_ + h * W_ + w), acc);
}

extern "C" void kernel_launch(void* const* d_in, const int* in_sizes, int n_in,
                              void* d_out, int out_size)
{
    const float* feat = (const float*)d_in[0];   // [8,64,128,128]
    const float* filt = (const float*)d_in[1];   // [8,576,128,128]
    float* out = (float*)d_out;                  // [8,64,128,128]

    // 2,097,152 threads -> 8192 blocks of 256 (8 warps/block, one row each)
    fac_leaky_kernel<<<8192, 256>>>(feat, filt, out);
}

// round 10
// speedup vs baseline: 1.2118x; 1.0330x over previous
#include <cuda_runtime.h>

// FAC 3x3 dynamic filtering + LeakyReLU(0.2)
// feature: [N=8, C=64, H=128, W=128] f32
// filters: [N, C*9, H, W] f32, channel index = c*9 + t, tap t = kh*3 + kw (row-major)
// out[n,c,h,w] = sum_{kh,kw} feat_zeropad[n,c,h+kh-1,w+kw-1] * filt[n,c*9+kh*3+kw,h,w]
// then leaky relu slope 0.2.
//
// Mapping: one warp = one (n,c,h) row (32 lanes x 4 px = 128 = W).
// All 12 vector loads (9 filter taps + 3 feature rows) are front-batched into
// registers to maximize per-warp MLP before any dependent math. Halo pixels
// come from warp shuffles; all control flow is warp-uniform.

#define N_ 8
#define C_ 64
#define H_ 128
#define W_ 128
#define HW_ (H_ * W_)

__global__ __launch_bounds__(256) void fac_leaky_kernel(
    const float* __restrict__ feat,
    const float* __restrict__ filt,
    float* __restrict__ out)
{
    int idx  = blockIdx.x * blockDim.x + threadIdx.x;
    int lane = idx & 31;
    int wrp  = idx >> 5;          // 65536 warps total
    int h    = wrp & 127;
    int nc   = wrp >> 7;          // 0..511
    int w    = lane << 2;

    const float*  fplane  = feat + nc * HW_ + w;
    const float4* filbase = reinterpret_cast<const float4*>(
        filt + (size_t)nc * 9 * HW_ + h * W_ + w);
    const float4 z4 = make_float4(0.f, 0.f, 0.f, 0.f);

    // ---- front-batched loads: 9 filter vectors ----
    float4 f0 = __ldcs(filbase + 0 * (HW_ / 4));
    float4 f1 = __ldcs(filbase + 1 * (HW_ / 4));
    float4 f2 = __ldcs(filbase + 2 * (HW_ / 4));
    float4 f3 = __ldcs(filbase + 3 * (HW_ / 4));
    float4 f4 = __ldcs(filbase + 4 * (HW_ / 4));
    float4 f5 = __ldcs(filbase + 5 * (HW_ / 4));
    float4 f6 = __ldcs(filbase + 6 * (HW_ / 4));
    float4 f7 = __ldcs(filbase + 7 * (HW_ / 4));
    float4 f8 = __ldcs(filbase + 8 * (HW_ / 4));

    // ---- front-batched loads: 3 feature rows (zero rows at v-boundary) ----
    float4 m0 = (h > 0)       ? __ldg(reinterpret_cast<const float4*>(fplane + (h - 1) * W_)) : z4;
    float4 m1 =                 __ldg(reinterpret_cast<const float4*>(fplane +  h      * W_));
    float4 m2 = (h < H_ - 1)  ? __ldg(reinterpret_cast<const float4*>(fplane + (h + 1) * W_)) : z4;

    // ---- halo via shuffles (cols w-1 and w+4 per row) ----
    float l0 = __shfl_up_sync(0xFFFFFFFFu, m0.w, 1);
    float l1 = __shfl_up_sync(0xFFFFFFFFu, m1.w, 1);
    float l2 = __shfl_up_sync(0xFFFFFFFFu, m2.w, 1);
    float r0 = __shfl_down_sync(0xFFFFFFFFu, m0.x, 1);
    float r1 = __shfl_down_sync(0xFFFFFFFFu, m1.x, 1);
    float r2 = __shfl_down_sync(0xFFFFFFFFu, m2.x, 1);
    if (lane == 0)  { l0 = 0.f; l1 = 0.f; l2 = 0.f; }
    if (lane == 31) { r0 = 0.f; r1 = 0.f; r2 = 0.f; }

    // ---- compute: acc[p] = sum_t e[row(t)][p + kw(t)] * f[t][p] ----
    float4 acc;
    // row 0 (kh=0): taps f0,f1,f2
    acc.x =          l0   * f0.x;
    acc.y =          m0.x * f0.y;
    acc.z =          m0.y * f0.z;
    acc.w =          m0.z * f0.w;
    acc.x = fmaf(m0.x, f1.x, acc.x);
    acc.y = fmaf(m0.y, f1.y, acc.y);
    acc.z = fmaf(m0.z, f1.z, acc.z);
    acc.w = fmaf(m0.w, f1.w, acc.w);
    acc.x = fmaf(m0.y, f2.x, acc.x);
    acc.y = fmaf(m0.z, f2.y, acc.y);
    acc.z = fmaf(m0.w, f2.z, acc.z);
    acc.w = fmaf(r0,   f2.w, acc.w);
    // row 1 (kh=1): taps f3,f4,f5
    acc.x = fmaf(l1,   f3.x, acc.x);
    acc.y = fmaf(m1.x, f3.y, acc.y);
    acc.z = fmaf(m1.y, f3.z, acc.z);
    acc.w = fmaf(m1.z, f3.w, acc.w);
    acc.x = fmaf(m1.x, f4.x, acc.x);
    acc.y = fmaf(m1.y, f4.y, acc.y);
    acc.z = fmaf(m1.z, f4.z, acc.z);
    acc.w = fmaf(m1.w, f4.w, acc.w);
    acc.x = fmaf(m1.y, f5.x, acc.x);
    acc.y = fmaf(m1.z, f5.y, acc.y);
    acc.z = fmaf(m1.w, f5.z, acc.z);
    acc.w = fmaf(r1,   f5.w, acc.w);
    // row 2 (kh=2): taps f6,f7,f8
    acc.x = fmaf(l2,   f6.x, acc.x);
    acc.y = fmaf(m2.x, f6.y, acc.y);
    acc.z = fmaf(m2.y, f6.z, acc.z);
    acc.w = fmaf(m2.z, f6.w, acc.w);
    acc.x = fmaf(m2.x, f7.x, acc.x);
    acc.y = fmaf(m2.y, f7.y, acc.y);
    acc.z = fmaf(m2.z, f7.z, acc.z);
    acc.w = fmaf(m2.w, f7.w, acc.w);
    acc.x = fmaf(m2.y, f8.x, acc.x);
    acc.y = fmaf(m2.z, f8.y, acc.y);
    acc.z = fmaf(m2.w, f8.z, acc.z);
    acc.w = fmaf(r2,   f8.w, acc.w);

    // LeakyReLU(0.2)
    acc.x = (acc.x >= 0.f) ? acc.x : 0.2f * acc.x;
    acc.y = (acc.y >= 0.f) ? acc.y : 0.2f * acc.y;
    acc.z = (acc.z >= 0.f) ? acc.z : 0.2f * acc.z;
    acc.w = (acc.w >= 0.f) ? acc.w : 0.2f * acc.w;

    __stcs(reinterpret_cast<float4*>(out + nc * HW_ + h * W_ + w), acc);
}

extern "C" void kernel_launch(void* const* d_in, const int* in_sizes, int n_in,
                              void* d_out, int out_size)
{
    const float* feat = (const float*)d_in[0];   // [8,64,128,128]
    const float* filt = (const float*)d_in[1];   // [8,576,128,128]
    float* out = (float*)d_out;                  // [8,64,128,128]

    fac_leaky_kernel<<<8192, 256>>>(feat, filt, out);
}